// round 4
// baseline (speedup 1.0000x reference)
#include <cuda_runtime.h>
#include <cstdint>

#define S  4096
#define H  256
#define NH 6
#define TH 768           // 3*H
#define LN_EPS 1e-5f

typedef unsigned long long u64;

// ---------------- scratch (static device globals: allocation-free) ----------
__device__ float g_x[S * H];                       // embedded tokens
__device__ float g_q[NH * S * H];
__device__ float g_k[NH * S * H];
__device__ float g_v[NH * S * H];
__device__ float g_att[(size_t)NH * S * S];        // 402 MB score/prob buffer
__device__ float g_o[S * NH * H];                  // concat head outputs
__device__ float g_pre[S * H];                     // x + attn (pre-LN)
__device__ float g_y[S * H];                       // LN output
__device__ float g_gi[S * TH];                     // precomputed input gates

// ---------------- small helpers ---------------------------------------------
__device__ __forceinline__ uint32_t smem_u32(const void* p) {
    return (uint32_t)__cvta_generic_to_shared(p);
}
__device__ __forceinline__ void st_cluster_f32(uint32_t saddr, uint32_t rank, float v) {
    uint32_t r;
    asm volatile("mapa.shared::cluster.u32 %0, %1, %2;" : "=r"(r) : "r"(saddr), "r"(rank));
    asm volatile("st.shared::cluster.f32 [%0], %1;" :: "r"(r), "f"(v) : "memory");
}
__device__ __forceinline__ void cluster_sync_() {
    asm volatile("barrier.cluster.arrive.aligned;" ::: "memory");
    asm volatile("barrier.cluster.wait.aligned;"   ::: "memory");
}

// ---------------- embedding gather ------------------------------------------
__global__ void embed_kernel(const int* __restrict__ tok,
                             const float* __restrict__ emb,
                             float* __restrict__ x) {
    const int s = blockIdx.x, d = threadIdx.x;
    x[s * H + d] = emb[(long)tok[s] * H + d];
}

// ---------------- 128x128x8 SGEMM, FFMA2 with duplicated-A smem --------------
// C[z][m][n] = scale * sum_k A[z][m][k] * (TRANSB ? B[z][n][k] : B[z][k][n])
//              (+ bias[z][n]) (+ resid[m][n])
// As holds each A element duplicated as an adjacent pair so the FFMA2
// a-operand is one broadcast LDS.64 (no mov.b64 packing, fewer regs).
template <bool TRANSB>
__global__ void __launch_bounds__(256, 2)
sgemm_kernel(const float* __restrict__ A, const float* __restrict__ B,
             float* __restrict__ C,
             int M, int N, int K,
             long sA, long sB, long sC, int ldc,
             const float* __restrict__ bias, int sBias,
             const float* __restrict__ resid, float scale) {
    __shared__ float As[8][258];   // 256 = 128 duplicated pairs (+2 pad)
    __shared__ float Bs[8][132];
    const int z = blockIdx.z;
    A += (long)z * sA;
    B += (long)z * sB;
    float* Cz = C + (long)z * sC;
    const int m0 = blockIdx.y * 128;
    const int n0 = blockIdx.x * 128;
    const int tid = threadIdx.x;
    const int arow = tid >> 1, ac4 = (tid & 1) * 4;
    const int ty = tid >> 4, tx = tid & 15;

    u64 acc[8][4];
#pragma unroll
    for (int i = 0; i < 8; i++)
#pragma unroll
        for (int j = 0; j < 4; j++) acc[i][j] = 0ull;

    for (int k0 = 0; k0 < K; k0 += 8) {
        // A panel: duplicated pairs
        float4 av = *(const float4*)&A[(long)(m0 + arow) * K + k0 + ac4];
        ((float2*)As[ac4 + 0])[arow] = make_float2(av.x, av.x);
        ((float2*)As[ac4 + 1])[arow] = make_float2(av.y, av.y);
        ((float2*)As[ac4 + 2])[arow] = make_float2(av.z, av.z);
        ((float2*)As[ac4 + 3])[arow] = make_float2(av.w, av.w);
        // B panel
        if (!TRANSB) {
            const int br = tid >> 5, bc4 = (tid & 31) * 4;
            float4 bv = *(const float4*)&B[(long)(k0 + br) * N + n0 + bc4];
            *(float4*)&Bs[br][bc4] = bv;
        } else {
            const int bn = tid >> 1, bk4 = (tid & 1) * 4;
            float4 bv = *(const float4*)&B[(long)(n0 + bn) * K + k0 + bk4];
            Bs[bk4 + 0][bn] = bv.x;
            Bs[bk4 + 1][bn] = bv.y;
            Bs[bk4 + 2][bn] = bv.z;
            Bs[bk4 + 3][bn] = bv.w;
        }
        __syncthreads();
#pragma unroll
        for (int k = 0; k < 8; k++) {
            const u64* a64 = (const u64*)As[k];
            const u64* b64 = (const u64*)&Bs[k][tx * 8];
            const u64 bp0 = b64[0], bp1 = b64[1], bp2 = b64[2], bp3 = b64[3];
#pragma unroll
            for (int i = 0; i < 8; i++) {
                const u64 ap = a64[ty * 8 + i];    // broadcast (a,a) pair
                asm("fma.rn.f32x2 %0, %1, %2, %0;" : "+l"(acc[i][0]) : "l"(ap), "l"(bp0));
                asm("fma.rn.f32x2 %0, %1, %2, %0;" : "+l"(acc[i][1]) : "l"(ap), "l"(bp1));
                asm("fma.rn.f32x2 %0, %1, %2, %0;" : "+l"(acc[i][2]) : "l"(ap), "l"(bp2));
                asm("fma.rn.f32x2 %0, %1, %2, %0;" : "+l"(acc[i][3]) : "l"(ap), "l"(bp3));
            }
        }
        __syncthreads();
    }
#pragma unroll
    for (int i = 0; i < 8; i++) {
        const int m = m0 + ty * 8 + i;
#pragma unroll
        for (int j = 0; j < 4; j++) {
            float2 p = *(float2*)&acc[i][j];
            const int n = n0 + tx * 8 + 2 * j;
            float v0 = p.x * scale, v1 = p.y * scale;
            if (bias) {
                v0 += bias[(long)sBias * z + n];
                v1 += bias[(long)sBias * z + n + 1];
            }
            if (resid) {
                v0 += resid[(long)m * N + n];
                v1 += resid[(long)m * N + n + 1];
            }
            Cz[(long)m * ldc + n]     = v0;
            Cz[(long)m * ldc + n + 1] = v1;
        }
    }
}

// ---------------- row softmax over 4096 (grid: (S, NH), 256 thr) -------------
__global__ void softmax_kernel(float* __restrict__ att) {
    float* p = att + ((long)blockIdx.y * S + blockIdx.x) * S;
    const int tid = threadIdx.x;
    __shared__ float red[8];
    float v[16];
    float mx = -3.4e38f;
#pragma unroll
    for (int r = 0; r < 16; r++) {
        v[r] = p[r * 256 + tid];
        mx = fmaxf(mx, v[r]);
    }
#pragma unroll
    for (int o = 16; o > 0; o >>= 1) mx = fmaxf(mx, __shfl_xor_sync(~0u, mx, o));
    if ((tid & 31) == 0) red[tid >> 5] = mx;
    __syncthreads();
    mx = red[0];
#pragma unroll
    for (int w = 1; w < 8; w++) mx = fmaxf(mx, red[w]);
    __syncthreads();

    float sum = 0.f;
#pragma unroll
    for (int r = 0; r < 16; r++) {
        v[r] = __expf(v[r] - mx);
        sum += v[r];
    }
#pragma unroll
    for (int o = 16; o > 0; o >>= 1) sum += __shfl_xor_sync(~0u, sum, o);
    if ((tid & 31) == 0) red[tid >> 5] = sum;
    __syncthreads();
    sum = 0.f;
#pragma unroll
    for (int w = 0; w < 8; w++) sum += red[w];
    const float inv = 1.f / sum;
#pragma unroll
    for (int r = 0; r < 16; r++) p[r * 256 + tid] = v[r] * inv;
}

// ---------------- LayerNorm (grid: S, 256 thr) --------------------------------
__global__ void ln_kernel(const float* __restrict__ pre,
                          const float* __restrict__ g,
                          const float* __restrict__ b,
                          float* __restrict__ y) {
    const int s = blockIdx.x, tid = threadIdx.x;
    __shared__ float red[8];
    float v = pre[s * H + tid];
    float sum = v;
#pragma unroll
    for (int o = 16; o > 0; o >>= 1) sum += __shfl_xor_sync(~0u, sum, o);
    if ((tid & 31) == 0) red[tid >> 5] = sum;
    __syncthreads();
    sum = 0.f;
#pragma unroll
    for (int w = 0; w < 8; w++) sum += red[w];
    const float mu = sum * (1.f / H);
    const float d = v - mu;
    __syncthreads();
    float s2 = d * d;
#pragma unroll
    for (int o = 16; o > 0; o >>= 1) s2 += __shfl_xor_sync(~0u, s2, o);
    if ((tid & 31) == 0) red[tid >> 5] = s2;
    __syncthreads();
    s2 = 0.f;
#pragma unroll
    for (int w = 0; w < 8; w++) s2 += red[w];
    const float var = s2 * (1.f / H);
    y[s * H + tid] = d * rsqrtf(var + LN_EPS) * g[tid] + b[tid];
}

// ---------------- GRU scan: 8-CTA cluster, W_hh in regs, cluster_sync --------
// (round-1 protocol: DSMEM broadcast + barrier.cluster — the mbarrier variant
//  regressed 6x in round 2, do not reintroduce)
__global__ void __cluster_dims__(8, 1, 1) __launch_bounds__(768, 1)
gru_kernel(const float* __restrict__ gi, const float* __restrict__ Whh,
           const float* __restrict__ bhh, float* __restrict__ out, int out_size) {
    __shared__ float h_s[2][H];
    __shared__ float gh_s[96];
    const int tid = threadIdx.x;
    const int cta = blockIdx.x;
    const int lr = tid >> 3, sub = tid & 7;   // gate-row 0..95, lane-in-row
    const int gate = lr >> 5;                 // 0:r 1:z 2:n
    const int iloc = lr & 31;
    const int grow = gate * H + cta * 32 + iloc;

    u64 w2[16];    // 32 contiguous columns as 16 f32x2 pairs
    const u64* wp = (const u64*)(Whh + (long)grow * H + sub * 32);
#pragma unroll
    for (int k = 0; k < 16; k++) w2[k] = wp[k];

    if (tid < H) h_s[0][tid] = 0.f;

    float bhr = 0.f, bhz = 0.f, bhn = 0.f;
    int gidx = 0;
    if (tid < 32) {
        gidx = cta * 32 + tid;
        bhr = bhh[gidx];
        bhz = bhh[H + gidx];
        bhn = bhh[2 * H + gidx];
    }
    const uint32_t h0a = smem_u32(&h_s[0][0]);
    const uint32_t h1a = smem_u32(&h_s[1][0]);
    cluster_sync_();

    for (int t = 0; t < S; t++) {
        const float* hb = h_s[t & 1];
        float ir = 0.f, iz = 0.f, in_ = 0.f;
        if (tid < 32) {   // prefetch input gates (latency hidden by matvec)
            const long base = (long)t * TH + gidx;
            ir = gi[base];
            iz = gi[base + H];
            in_ = gi[base + 2 * H];
        }
        u64 acc2 = 0ull;
        const u64* h2 = (const u64*)(hb + sub * 32);
#pragma unroll
        for (int k = 0; k < 16; k++) {
            const u64 hv = h2[k];
            asm("fma.rn.f32x2 %0, %1, %2, %0;" : "+l"(acc2) : "l"(w2[k]), "l"(hv));
        }
        float2 af = *(float2*)&acc2;
        float acc = af.x + af.y;
        acc += __shfl_xor_sync(~0u, acc, 4);
        acc += __shfl_xor_sync(~0u, acc, 2);
        acc += __shfl_xor_sync(~0u, acc, 1);
        if (sub == 0) gh_s[lr] = acc;
        __syncthreads();
        if (tid < 32) {
            const float hr = gh_s[tid] + bhr;
            const float hz = gh_s[32 + tid] + bhz;
            const float hn = gh_s[64 + tid] + bhn;
            const float r  = 1.f / (1.f + __expf(-(ir + hr)));
            const float zg = 1.f / (1.f + __expf(-(iz + hz)));
            const float n  = tanhf(in_ + r * hn);
            const float hnew = (1.f - zg) * n + zg * hb[gidx];
            const uint32_t dst = ((t & 1) ? h0a : h1a) + (uint32_t)gidx * 4u;
#pragma unroll
            for (uint32_t p = 0; p < 8; p++) st_cluster_f32(dst, p, hnew);
        }
        cluster_sync_();
    }
    if (cta == 0 && tid < H) {
        const float hv = h_s[0][tid];   // after t=4095 (odd), final h is in buf 0
        out[tid] = hv;
        if (out_size >= 2 * H) out[H + tid] = hv;
    }
}

// ---------------- host orchestration ----------------------------------------
extern "C" void kernel_launch(void* const* d_in, const int* in_sizes, int n_in,
                              void* d_out, int out_size) {
    const int*   tokens = (const int*)  d_in[0];
    const float* emb    = (const float*)d_in[1];
    const float* Wq     = (const float*)d_in[2];
    const float* bq     = (const float*)d_in[3];
    const float* Wk     = (const float*)d_in[4];
    const float* bk     = (const float*)d_in[5];
    const float* Wv     = (const float*)d_in[6];
    const float* bv     = (const float*)d_in[7];
    const float* Wo     = (const float*)d_in[8];
    const float* bo     = (const float*)d_in[9];
    const float* ln_g   = (const float*)d_in[10];
    const float* ln_b   = (const float*)d_in[11];
    const float* W_ih   = (const float*)d_in[12];
    const float* W_hh   = (const float*)d_in[13];
    const float* b_ih   = (const float*)d_in[14];
    const float* b_hh   = (const float*)d_in[15];
    (void)in_sizes; (void)n_in;

    float *x, *q, *k, *v, *att, *o, *pre, *y, *gi;
    cudaGetSymbolAddress((void**)&x,   g_x);
    cudaGetSymbolAddress((void**)&q,   g_q);
    cudaGetSymbolAddress((void**)&k,   g_k);
    cudaGetSymbolAddress((void**)&v,   g_v);
    cudaGetSymbolAddress((void**)&att, g_att);
    cudaGetSymbolAddress((void**)&o,   g_o);
    cudaGetSymbolAddress((void**)&pre, g_pre);
    cudaGetSymbolAddress((void**)&y,   g_y);
    cudaGetSymbolAddress((void**)&gi,  g_gi);

    embed_kernel<<<S, H>>>(tokens, emb, x);

    // q/k/v: [4096,256] @ [256,256] per head, bias per head
    const dim3 gQKV(2, 32, NH);
    sgemm_kernel<false><<<gQKV, 256>>>(x, Wq, q, S, H, H, 0, (long)H * H,
                                       (long)S * H, H, bq, H, nullptr, 1.f);
    sgemm_kernel<false><<<gQKV, 256>>>(x, Wk, k, S, H, H, 0, (long)H * H,
                                       (long)S * H, H, bk, H, nullptr, 1.f);
    sgemm_kernel<false><<<gQKV, 256>>>(x, Wv, v, S, H, H, 0, (long)H * H,
                                       (long)S * H, H, bv, H, nullptr, 1.f);

    // scores = q @ k^T / sqrt(H)
    sgemm_kernel<true><<<dim3(32, 32, NH), 256>>>(q, k, att, S, S, H,
                                                  (long)S * H, (long)S * H,
                                                  (long)S * S, S,
                                                  nullptr, 0, nullptr, 1.f / 16.f);
    softmax_kernel<<<dim3(S, NH), 256>>>(att);

    // o[s, h*H+e] = att[h] @ v[h]   (ldc = NH*H, per-head column offset)
    sgemm_kernel<false><<<dim3(2, 32, NH), 256>>>(att, v, o, S, H, S,
                                                  (long)S * S, (long)S * H,
                                                  (long)H, NH * H,
                                                  nullptr, 0, nullptr, 1.f);

    // pre = x + o @ Wo + bo
    sgemm_kernel<false><<<dim3(2, 32, 1), 256>>>(o, Wo, pre, S, H, NH * H,
                                                 0, 0, 0, H, bo, 0, x, 1.f);
    ln_kernel<<<S, H>>>(pre, ln_g, ln_b, y);

    // gi = y @ W_ih^T + b_ih
    sgemm_kernel<true><<<dim3(6, 32, 1), 256>>>(y, W_ih, gi, S, TH, H,
                                                0, 0, 0, TH, b_ih, 0, nullptr, 1.f);

    gru_kernel<<<8, 768>>>(gi, W_hh, b_hh, (float*)d_out, out_size);
}

// round 6
// speedup vs baseline: 3.2902x; 3.2902x over previous
#include <cuda_runtime.h>
#include <cstdint>

#define S  4096
#define H  256
#define NH 6
#define TH 768           // 3*H
#define LN_EPS 1e-5f

typedef unsigned long long u64;

// ---------------- scratch (static device globals: allocation-free) ----------
__device__ float g_x[S * H];
__device__ float g_q[NH * S * H];
__device__ float g_k[NH * S * H];
__device__ float g_v[NH * S * H];
__device__ float g_att[(size_t)NH * S * S];
__device__ float g_o[S * NH * H];
__device__ float g_pre[S * H];
__device__ float g_y[S * H];
__device__ float g_gi[S * TH];

// ---------------- small helpers ---------------------------------------------
__device__ __forceinline__ uint32_t smem_u32(const void* p) {
    return (uint32_t)__cvta_generic_to_shared(p);
}
__device__ __forceinline__ void st_cluster_f32(uint32_t saddr, uint32_t rank, float v) {
    uint32_t r;
    asm volatile("mapa.shared::cluster.u32 %0, %1, %2;" : "=r"(r) : "r"(saddr), "r"(rank));
    asm volatile("st.shared::cluster.f32 [%0], %1;" :: "r"(r), "f"(v) : "memory");
}
__device__ __forceinline__ void cluster_sync_() {
    asm volatile("barrier.cluster.arrive.aligned;" ::: "memory");
    asm volatile("barrier.cluster.wait.aligned;"   ::: "memory");
}
__device__ __forceinline__ uint32_t f2tf32(float v) {
    uint32_t t;
    asm("cvt.rna.tf32.f32 %0, %1;" : "=r"(t) : "f"(v));
    return t;
}

// ---------------- embedding gather ------------------------------------------
__global__ void embed_kernel(const int* __restrict__ tok,
                             const float* __restrict__ emb,
                             float* __restrict__ x) {
    const int s = blockIdx.x, d = threadIdx.x;
    x[s * H + d] = emb[(long)tok[s] * H + d];
}

// ---------------- tf32 mma.sync GEMM, 128x128 block, K-panel 32 --------------
// C[z][m][n] = scale * sum_k A[z][m][k] * (TRANSB ? B[z][n][k] : B[z][k][n])
//              (+ bias[z][n]) (+ resid[m][n])
// Requires M%128==0, N%128==0, K%32==0 (true for all uses here).
// Smem panels stored [mn][k] with stride 36 -> fragment LDS conflict-free.
#define KP 32
#define SSTR 36
template <bool TRANSB>
__global__ void __launch_bounds__(256)
mma_gemm(const float* __restrict__ A, const float* __restrict__ B,
         float* __restrict__ C,
         int M, int N, int K,
         long sA, long sB, long sC, int ldc,
         const float* __restrict__ bias, int sBias,
         const float* __restrict__ resid, float scale) {
    __shared__ uint32_t As[128 * SSTR];
    __shared__ uint32_t Bs[128 * SSTR];
    const int z = blockIdx.z;
    A += (long)z * sA;
    B += (long)z * sB;
    float* Cz = C + (long)z * sC;
    const int m0 = blockIdx.y * 128;
    const int n0 = blockIdx.x * 128;
    const int tid  = threadIdx.x;
    const int wid  = tid >> 5, lane = tid & 31;
    const int wm   = (wid & 1) * 64;      // warp row offset   (2 warps in M)
    const int wn   = (wid >> 1) * 32;     // warp col offset   (4 warps in N)
    const int gr   = lane >> 2;           // group row 0..7
    const int gc   = lane & 3;            // group col 0..3

    float acc[4][4][4];
#pragma unroll
    for (int i = 0; i < 4; i++)
#pragma unroll
        for (int j = 0; j < 4; j++)
#pragma unroll
            for (int r = 0; r < 4; r++) acc[i][j][r] = 0.f;

    for (int k0 = 0; k0 < K; k0 += KP) {
        // ---- fill As: 128 rows x 32 k, cvt to tf32 ----
#pragma unroll
        for (int i = 0; i < 4; i++) {
            const int lin = tid + i * 256;          // 0..1023 float4 slots
            const int row = lin >> 3, c4 = (lin & 7) * 4;
            float4 v = *(const float4*)&A[(long)(m0 + row) * K + k0 + c4];
            uint32_t* d = &As[row * SSTR + c4];
            d[0] = f2tf32(v.x); d[1] = f2tf32(v.y);
            d[2] = f2tf32(v.z); d[3] = f2tf32(v.w);
        }
        // ---- fill Bs[n][k] ----
        if (TRANSB) {
#pragma unroll
            for (int i = 0; i < 4; i++) {
                const int lin = tid + i * 256;
                const int row = lin >> 3, c4 = (lin & 7) * 4;
                float4 v = *(const float4*)&B[(long)(n0 + row) * K + k0 + c4];
                uint32_t* d = &Bs[row * SSTR + c4];
                d[0] = f2tf32(v.x); d[1] = f2tf32(v.y);
                d[2] = f2tf32(v.z); d[3] = f2tf32(v.w);
            }
        } else {
#pragma unroll
            for (int i = 0; i < 4; i++) {
                const int lin = tid + i * 256;
                const int k = lin >> 5, n4 = (lin & 31) * 4;   // transpose copy
                float4 v = *(const float4*)&B[(long)(k0 + k) * N + n0 + n4];
                Bs[(n4 + 0) * SSTR + k] = f2tf32(v.x);
                Bs[(n4 + 1) * SSTR + k] = f2tf32(v.y);
                Bs[(n4 + 2) * SSTR + k] = f2tf32(v.z);
                Bs[(n4 + 3) * SSTR + k] = f2tf32(v.w);
            }
        }
        __syncthreads();

        // ---- 4 x k8 mma steps ----
#pragma unroll
        for (int kk = 0; kk < 4; kk++) {
            const int kb = kk * 8;
            uint32_t a[4][4], b[4][2];
#pragma unroll
            for (int mt = 0; mt < 4; mt++) {
                const int r0 = wm + mt * 16 + gr;
                a[mt][0] = As[(r0    ) * SSTR + kb + gc];
                a[mt][1] = As[(r0 + 8) * SSTR + kb + gc];
                a[mt][2] = As[(r0    ) * SSTR + kb + gc + 4];
                a[mt][3] = As[(r0 + 8) * SSTR + kb + gc + 4];
            }
#pragma unroll
            for (int nt = 0; nt < 4; nt++) {
                const int n = wn + nt * 8 + gr;
                b[nt][0] = Bs[n * SSTR + kb + gc];
                b[nt][1] = Bs[n * SSTR + kb + gc + 4];
            }
#pragma unroll
            for (int mt = 0; mt < 4; mt++)
#pragma unroll
                for (int nt = 0; nt < 4; nt++) {
                    float* c = acc[mt][nt];
                    asm volatile(
                        "mma.sync.aligned.m16n8k8.row.col.f32.tf32.tf32.f32 "
                        "{%0,%1,%2,%3}, {%4,%5,%6,%7}, {%8,%9}, {%0,%1,%2,%3};"
                        : "+f"(c[0]), "+f"(c[1]), "+f"(c[2]), "+f"(c[3])
                        : "r"(a[mt][0]), "r"(a[mt][1]), "r"(a[mt][2]), "r"(a[mt][3]),
                          "r"(b[nt][0]), "r"(b[nt][1]));
                }
        }
        __syncthreads();
    }

    // ---- epilogue ----
#pragma unroll
    for (int mt = 0; mt < 4; mt++) {
#pragma unroll
        for (int nt = 0; nt < 4; nt++) {
            const float* c = acc[mt][nt];
#pragma unroll
            for (int half = 0; half < 2; half++) {
                const int m = m0 + wm + mt * 16 + gr + half * 8;
                const int n = n0 + wn + nt * 8 + gc * 2;
                float v0 = c[half * 2 + 0] * scale;
                float v1 = c[half * 2 + 1] * scale;
                if (bias) {
                    v0 += bias[(long)sBias * z + n];
                    v1 += bias[(long)sBias * z + n + 1];
                }
                if (resid) {
                    v0 += resid[(long)m * N + n];
                    v1 += resid[(long)m * N + n + 1];
                }
                Cz[(long)m * ldc + n]     = v0;
                Cz[(long)m * ldc + n + 1] = v1;
            }
        }
    }
}

// ---------------- row softmax over 4096 (grid: (S, NH), 256 thr) -------------
__global__ void softmax_kernel(float* __restrict__ att) {
    float* p = att + ((long)blockIdx.y * S + blockIdx.x) * S;
    const int tid = threadIdx.x;
    __shared__ float red[8];
    float v[16];
    float mx = -3.4e38f;
#pragma unroll
    for (int r = 0; r < 16; r++) {
        v[r] = p[r * 256 + tid];
        mx = fmaxf(mx, v[r]);
    }
#pragma unroll
    for (int o = 16; o > 0; o >>= 1) mx = fmaxf(mx, __shfl_xor_sync(~0u, mx, o));
    if ((tid & 31) == 0) red[tid >> 5] = mx;
    __syncthreads();
    mx = red[0];
#pragma unroll
    for (int w = 1; w < 8; w++) mx = fmaxf(mx, red[w]);
    __syncthreads();

    float sum = 0.f;
#pragma unroll
    for (int r = 0; r < 16; r++) {
        v[r] = __expf(v[r] - mx);
        sum += v[r];
    }
#pragma unroll
    for (int o = 16; o > 0; o >>= 1) sum += __shfl_xor_sync(~0u, sum, o);
    if ((tid & 31) == 0) red[tid >> 5] = sum;
    __syncthreads();
    sum = 0.f;
#pragma unroll
    for (int w = 0; w < 8; w++) sum += red[w];
    const float inv = 1.f / sum;
#pragma unroll
    for (int r = 0; r < 16; r++) p[r * 256 + tid] = v[r] * inv;
}

// ---------------- LayerNorm (grid: S, 256 thr) --------------------------------
__global__ void ln_kernel(const float* __restrict__ pre,
                          const float* __restrict__ g,
                          const float* __restrict__ b,
                          float* __restrict__ y) {
    const int s = blockIdx.x, tid = threadIdx.x;
    __shared__ float red[8];
    float v = pre[s * H + tid];
    float sum = v;
#pragma unroll
    for (int o = 16; o > 0; o >>= 1) sum += __shfl_xor_sync(~0u, sum, o);
    if ((tid & 31) == 0) red[tid >> 5] = sum;
    __syncthreads();
    sum = 0.f;
#pragma unroll
    for (int w = 0; w < 8; w++) sum += red[w];
    const float mu = sum * (1.f / H);
    const float d = v - mu;
    __syncthreads();
    float s2 = d * d;
#pragma unroll
    for (int o = 16; o > 0; o >>= 1) s2 += __shfl_xor_sync(~0u, s2, o);
    if ((tid & 31) == 0) red[tid >> 5] = s2;
    __syncthreads();
    s2 = 0.f;
#pragma unroll
    for (int w = 0; w < 8; w++) s2 += red[w];
    const float var = s2 * (1.f / H);
    y[s * H + tid] = d * rsqrtf(var + LN_EPS) * g[tid] + b[tid];
}

// ---------------- GRU scan: 8-CTA cluster (round-1 proven protocol) ----------
__global__ void __cluster_dims__(8, 1, 1) __launch_bounds__(768, 1)
gru_kernel(const float* __restrict__ gi, const float* __restrict__ Whh,
           const float* __restrict__ bhh, float* __restrict__ out, int out_size) {
    __shared__ float h_s[2][H];
    __shared__ float gh_s[96];
    const int tid = threadIdx.x;
    const int cta = blockIdx.x;
    const int lr = tid >> 3, sub = tid & 7;
    const int gate = lr >> 5;
    const int iloc = lr & 31;
    const int grow = gate * H + cta * 32 + iloc;

    float w[32];
#pragma unroll
    for (int k = 0; k < 32; k++) w[k] = Whh[grow * H + sub + 8 * k];

    if (tid < H) h_s[0][tid] = 0.f;

    float bhr = 0.f, bhz = 0.f, bhn = 0.f;
    int gidx = 0;
    if (tid < 32) {
        gidx = cta * 32 + tid;
        bhr = bhh[gidx];
        bhz = bhh[H + gidx];
        bhn = bhh[2 * H + gidx];
    }
    const uint32_t h0a = smem_u32(&h_s[0][0]);
    const uint32_t h1a = smem_u32(&h_s[1][0]);
    cluster_sync_();

    for (int t = 0; t < S; t++) {
        const float* hb = h_s[t & 1];
        float ir = 0.f, iz = 0.f, in_ = 0.f;
        if (tid < 32) {
            const long base = (long)t * TH + gidx;
            ir = gi[base];
            iz = gi[base + H];
            in_ = gi[base + 2 * H];
        }
        float acc = 0.f;
#pragma unroll
        for (int k = 0; k < 32; k++) acc += w[k] * hb[sub + 8 * k];
        acc += __shfl_xor_sync(~0u, acc, 4);
        acc += __shfl_xor_sync(~0u, acc, 2);
        acc += __shfl_xor_sync(~0u, acc, 1);
        if (sub == 0) gh_s[lr] = acc;
        __syncthreads();
        if (tid < 32) {
            const float hr = gh_s[tid] + bhr;
            const float hz = gh_s[32 + tid] + bhz;
            const float hn = gh_s[64 + tid] + bhn;
            const float r  = 1.f / (1.f + __expf(-(ir + hr)));
            const float zg = 1.f / (1.f + __expf(-(iz + hz)));
            const float n  = tanhf(in_ + r * hn);
            const float hnew = (1.f - zg) * n + zg * hb[gidx];
            const uint32_t dst = ((t & 1) ? h0a : h1a) + (uint32_t)gidx * 4u;
#pragma unroll
            for (uint32_t p = 0; p < 8; p++) st_cluster_f32(dst, p, hnew);
        }
        cluster_sync_();
    }
    if (cta == 0 && tid < H) {
        const float hv = h_s[0][tid];
        out[tid] = hv;
        if (out_size >= 2 * H) out[H + tid] = hv;
    }
}

// ---------------- host orchestration ----------------------------------------
extern "C" void kernel_launch(void* const* d_in, const int* in_sizes, int n_in,
                              void* d_out, int out_size) {
    const int*   tokens = (const int*)  d_in[0];
    const float* emb    = (const float*)d_in[1];
    const float* Wq     = (const float*)d_in[2];
    const float* bq     = (const float*)d_in[3];
    const float* Wk     = (const float*)d_in[4];
    const float* bk     = (const float*)d_in[5];
    const float* Wv     = (const float*)d_in[6];
    const float* bv     = (const float*)d_in[7];
    const float* Wo     = (const float*)d_in[8];
    const float* bo     = (const float*)d_in[9];
    const float* ln_g   = (const float*)d_in[10];
    const float* ln_b   = (const float*)d_in[11];
    const float* W_ih   = (const float*)d_in[12];
    const float* W_hh   = (const float*)d_in[13];
    const float* b_ih   = (const float*)d_in[14];
    const float* b_hh   = (const float*)d_in[15];
    (void)in_sizes; (void)n_in;

    float *x, *q, *k, *v, *att, *o, *pre, *y, *gi;
    cudaGetSymbolAddress((void**)&x,   g_x);
    cudaGetSymbolAddress((void**)&q,   g_q);
    cudaGetSymbolAddress((void**)&k,   g_k);
    cudaGetSymbolAddress((void**)&v,   g_v);
    cudaGetSymbolAddress((void**)&att, g_att);
    cudaGetSymbolAddress((void**)&o,   g_o);
    cudaGetSymbolAddress((void**)&pre, g_pre);
    cudaGetSymbolAddress((void**)&y,   g_y);
    cudaGetSymbolAddress((void**)&gi,  g_gi);

    embed_kernel<<<S, H>>>(tokens, emb, x);

    // q/k/v: [4096,256] @ [256,256] per head, bias per head
    const dim3 gQKV(2, 32, NH);
    mma_gemm<false><<<gQKV, 256>>>(x, Wq, q, S, H, H, 0, (long)H * H,
                                   (long)S * H, H, bq, H, nullptr, 1.f);
    mma_gemm<false><<<gQKV, 256>>>(x, Wk, k, S, H, H, 0, (long)H * H,
                                   (long)S * H, H, bk, H, nullptr, 1.f);
    mma_gemm<false><<<gQKV, 256>>>(x, Wv, v, S, H, H, 0, (long)H * H,
                                   (long)S * H, H, bv, H, nullptr, 1.f);

    // scores = q @ k^T / sqrt(H)
    mma_gemm<true><<<dim3(32, 32, NH), 256>>>(q, k, att, S, S, H,
                                              (long)S * H, (long)S * H,
                                              (long)S * S, S,
                                              nullptr, 0, nullptr, 1.f / 16.f);
    softmax_kernel<<<dim3(S, NH), 256>>>(att);

    // o[s, h*H+e] = att[h] @ v[h]   (ldc = NH*H, per-head column offset)
    mma_gemm<false><<<dim3(2, 32, NH), 256>>>(att, v, o, S, H, S,
                                              (long)S * S, (long)S * H,
                                              (long)H, NH * H,
                                              nullptr, 0, nullptr, 1.f);

    // pre = x + o @ Wo + bo
    mma_gemm<false><<<dim3(2, 32, 1), 256>>>(o, Wo, pre, S, H, NH * H,
                                             0, 0, 0, H, bo, 0, x, 1.f);
    ln_kernel<<<S, H>>>(pre, ln_g, ln_b, y);

    // gi = y @ W_ih^T + b_ih
    mma_gemm<true><<<dim3(6, 32, 1), 256>>>(y, W_ih, gi, S, TH, H,
                                            0, 0, 0, TH, b_ih, 0, nullptr, 1.f);

    gru_kernel<<<8, 768>>>(gi, W_hh, b_hh, (float*)d_out, out_size);
}